// round 17
// baseline (speedup 1.0000x reference)
#include <cuda_runtime.h>
#include <cuda_fp16.h>
#include <math.h>
#include <stdint.h>

#define T_TOK 8192
#define H 1024
#define E 8
#define CAP 1024   // capacity = T/E

// ---------------- scratch (no allocations allowed) ----------------
__device__ int   g_expert_idx[T_TOK];
__device__ float g_gate[T_TOK];
__device__ int   g_slot_token[E * CAP];   // token id per (expert, slot), -1 if empty
__device__ unsigned char g_dropped[T_TOK];
__device__ __align__(256) __half g_Wh[E * H * H];    // 16 MB (fp16 W)
__device__ __align__(256) __half g_xh[T_TOK * H];    // 16 MB (fp16 x, token order)

// ---------------- kernel 1: fused routing (+fp16 x) and W->fp16 conversion ----------------
// blocks [0, 1024): routing, 8 warps = 8 tokens per block
// blocks [1024, 3072): W conversion, 16 elems/thread
__global__ void route_conv_kernel(const float* __restrict__ x,
                                  const float* __restrict__ wg,
                                  const float* __restrict__ W) {
    if (blockIdx.x >= 1024) {
        // ---- W conversion part (independent of routing) ----
        size_t base = ((size_t)(blockIdx.x - 1024) * 256 + threadIdx.x) * 16;
        float4 a0 = *(const float4*)(W + base);
        float4 a1 = *(const float4*)(W + base + 4);
        float4 a2 = *(const float4*)(W + base + 8);
        float4 a3 = *(const float4*)(W + base + 12);
        float v[16] = {a0.x,a0.y,a0.z,a0.w, a1.x,a1.y,a1.z,a1.w,
                       a2.x,a2.y,a2.z,a2.w, a3.x,a3.y,a3.z,a3.w};
        __half h[16];
#pragma unroll
        for (int i = 0; i < 16; i++) h[i] = __float2half_rn(v[i]);
        *(uint4*)(g_Wh + base)     = ((uint4*)h)[0];
        *(uint4*)(g_Wh + base + 8) = ((uint4*)h)[1];
        return;
    }

    // ---- routing part ----
    __shared__ float s_wg[H * E];
    for (int i = threadIdx.x; i < H * E; i += blockDim.x) s_wg[i] = wg[i];
    __syncthreads();

    int warp = (blockIdx.x * blockDim.x + threadIdx.x) >> 5;
    int lane = threadIdx.x & 31;

    const float* xp = x + (size_t)warp * H;
    __half* xh = g_xh + (size_t)warp * H;
    float acc[E];
#pragma unroll
    for (int e = 0; e < E; e++) acc[e] = 0.f;
    for (int k = lane; k < H; k += 32) {
        float xv = xp[k];
        xh[k] = __float2half_rn(xv);          // emit fp16 copy (A-conv fused)
        const float* w = s_wg + k * E;
#pragma unroll
        for (int e = 0; e < E; e++) acc[e] = fmaf(xv, w[e], acc[e]);
    }
#pragma unroll
    for (int e = 0; e < E; e++) {
#pragma unroll
        for (int o = 16; o > 0; o >>= 1)
            acc[e] += __shfl_down_sync(0xffffffffu, acc[e], o);
    }
    if (lane == 0) {
        float m = acc[0]; int bi = 0;
#pragma unroll
        for (int e = 1; e < E; e++)
            if (acc[e] > m) { m = acc[e]; bi = e; }
        float s = 0.f;
#pragma unroll
        for (int e = 0; e < E; e++) s += expf(acc[e] - m);
        g_expert_idx[warp] = bi;
        g_gate[warp]       = 1.f / s;
    }
}

// ---------------- kernel 2: order-preserving scan (warp-shuffle) ----------------
__global__ void scan_kernel() {
    __shared__ unsigned long long w0[32], w1[32];
    const int tid = threadIdx.x;
    const int lane = tid & 31, wid = tid >> 5;

    const int base = tid * 8;
    int eidx[8];
    unsigned long long c0 = 0ULL, c1 = 0ULL;
#pragma unroll
    for (int j = 0; j < 8; j++) {
        int e = g_expert_idx[base + j];
        eidx[j] = e;
        if (e < 4) c0 += 1ULL << (16 * e);
        else       c1 += 1ULL << (16 * (e - 4));
    }
    unsigned long long s0 = c0, s1 = c1;
#pragma unroll
    for (int d = 1; d < 32; d <<= 1) {
        unsigned long long t0 = __shfl_up_sync(0xffffffffu, s0, d);
        unsigned long long t1 = __shfl_up_sync(0xffffffffu, s1, d);
        if (lane >= d) { s0 += t0; s1 += t1; }
    }
    if (lane == 31) { w0[wid] = s0; w1[wid] = s1; }

    for (int i = tid; i < E * CAP; i += 1024) g_slot_token[i] = -1;
    __syncthreads();
    if (wid == 0) {
        unsigned long long v0 = w0[lane], v1 = w1[lane];
#pragma unroll
        for (int d = 1; d < 32; d <<= 1) {
            unsigned long long t0 = __shfl_up_sync(0xffffffffu, v0, d);
            unsigned long long t1 = __shfl_up_sync(0xffffffffu, v1, d);
            if (lane >= d) { v0 += t0; v1 += t1; }
        }
        w0[lane] = v0; w1[lane] = v1;
    }
    __syncthreads();
    unsigned long long o0 = s0 - c0 + (wid > 0 ? w0[wid - 1] : 0ULL);
    unsigned long long o1 = s1 - c1 + (wid > 0 ? w1[wid - 1] : 0ULL);

    int off[E];
#pragma unroll
    for (int e = 0; e < 4; e++) {
        off[e]     = (int)((o0 >> (16 * e)) & 0xFFFFULL);
        off[e + 4] = (int)((o1 >> (16 * e)) & 0xFFFFULL);
    }
#pragma unroll
    for (int j = 0; j < 8; j++) {
        int t = base + j;
        int e = eidx[j];
        int p = 0;
#pragma unroll
        for (int q = 0; q < E; q++)
            if (e == q) { p = off[q]; off[q] = p + 1; }
        if (p < CAP) { g_slot_token[e * CAP + p] = t; g_dropped[t] = 0; }
        else         { g_dropped[t] = 1; }
    }
}

// ---------------- kernel 3: GEMM + folded dropped-row zeroing ----------------
// grid (9, 64): blockIdx.x < 8 -> GEMM tile; blockIdx.x == 8 -> zero dropped rows
#define BM 128
#define BN 128
#define BK 64                       // fp16 per chunk = 128B rows
#define ROW_B 128                   // bytes per smem row
#define PLANE_B (BM * ROW_B)        // 16384
#define CHUNK_B (2 * PLANE_B)       // 32768 (A plane + B plane)
#define STAGE_B (2 * CHUNK_B)       // 65536 (2 chunks per stage)
#define NSTAGE 3
#define NITER 8                     // H / (2*BK)
#define SMEM_TOK 512
#define GEMM_SMEM (SMEM_TOK + NSTAGE * STAGE_B)   // 197120

__device__ __forceinline__ uint32_t smem_u32(const void* p) {
    uint32_t a;
    asm("{ .reg .u64 t; cvta.to.shared.u64 t, %1; cvt.u32.u64 %0, t; }" : "=r"(a) : "l"(p));
    return a;
}
__device__ __forceinline__ void cpasync16(uint32_t dst, const void* src) {
    asm volatile("cp.async.cg.shared.global [%0], [%1], 16;" :: "r"(dst), "l"(src));
}
__device__ __forceinline__ void cpasync16z(uint32_t dst, const void* src, uint32_t sz) {
    asm volatile("cp.async.cg.shared.global [%0], [%1], 16, %2;" :: "r"(dst), "l"(src), "r"(sz));
}
__device__ __forceinline__ void ldsm4(uint32_t& r0, uint32_t& r1, uint32_t& r2, uint32_t& r3,
                                      uint32_t addr) {
    asm volatile("ldmatrix.sync.aligned.m8n8.x4.shared.b16 {%0,%1,%2,%3}, [%4];"
                 : "=r"(r0), "=r"(r1), "=r"(r2), "=r"(r3) : "r"(addr));
}
__device__ __forceinline__ void mma16816(float* d, const uint32_t* a, uint32_t b0, uint32_t b1) {
    asm volatile("mma.sync.aligned.m16n8k16.row.col.f32.f16.f16.f32 "
                 "{%0,%1,%2,%3}, {%4,%5,%6,%7}, {%8,%9}, {%0,%1,%2,%3};"
                 : "+f"(d[0]), "+f"(d[1]), "+f"(d[2]), "+f"(d[3])
                 : "r"(a[0]), "r"(a[1]), "r"(a[2]), "r"(a[3]), "r"(b0), "r"(b1));
}

__global__ void __launch_bounds__(512, 1)
moe_gemm(const float* __restrict__ bias, float* __restrict__ out) {
    const int tid = threadIdx.x;

    // ---- folded zeroing path: disjoint rows (dropped tokens only) ----
    if (blockIdx.x == 8) {
        const int tbase = blockIdx.y * 128;
        for (int j = tid; j < 128 * 256; j += 512) {
            int t = tbase + (j >> 8);
            if (g_dropped[t])
                ((float4*)(out + (size_t)t * H))[j & 255] = make_float4(0.f, 0.f, 0.f, 0.f);
        }
        return;
    }

    extern __shared__ char smem[];
    int* s_tok = (int*)smem;
    const uint32_t sbase = smem_u32(smem) + SMEM_TOK;

    const int lane = tid & 31;
    const int wid  = tid >> 5;             // 0..15, warp grid 4(M) x 4(N)
    const int bm = blockIdx.y * BM;
    const int bn = blockIdx.x * BN;
    const int e  = bm >> 10;

    if (tid < BM) s_tok[tid] = g_slot_token[bm + tid];

    // ---- cp.async mapping: row = tid>>2 (4 thr/row), 2 x 16B segs each ----
    const int crow = tid >> 2;
    const int s0   = (tid & 3) * 2;
    const uint32_t d0 = (uint32_t)(crow * ROW_B + ((s0     ^ (crow & 7)) * 16));
    const uint32_t d1 = (uint32_t)(crow * ROW_B + (((s0+1) ^ (crow & 7)) * 16));
    const int atok = g_slot_token[bm + crow];
    const uint32_t asz = (atok >= 0) ? 16u : 0u;
    const __half* pA  = g_xh + (size_t)(atok >= 0 ? atok : 0) * H + s0 * 8;
    const __half* pB  = g_Wh + ((size_t)e * H + bn + crow) * H + s0 * 8;

// stage = 2 chunks: [A0|B0|A1|B1], one commit per stage
#define ISSUE_STAGE(stg, it) do { \
        uint32_t db = sbase + (stg) * STAGE_B; \
        int ko = (it) * (2 * BK); \
        cpasync16z(db + d0,                      pA + ko,          asz); \
        cpasync16z(db + d1,                      pA + ko + 8,      asz); \
        cpasync16(db + PLANE_B + d0,             pB + ko); \
        cpasync16(db + PLANE_B + d1,             pB + ko + 8); \
        cpasync16z(db + CHUNK_B + d0,            pA + ko + BK,     asz); \
        cpasync16z(db + CHUNK_B + d1,            pA + ko + BK + 8, asz); \
        cpasync16(db + CHUNK_B + PLANE_B + d0,   pB + ko + BK); \
        cpasync16(db + CHUNK_B + PLANE_B + d1,   pB + ko + BK + 8); \
        asm volatile("cp.async.commit_group;" ::: "memory"); \
    } while (0)

    float D[2][4][4];
#pragma unroll
    for (int mt = 0; mt < 2; mt++)
#pragma unroll
        for (int nt = 0; nt < 4; nt++)
#pragma unroll
            for (int r = 0; r < 4; r++) D[mt][nt][r] = 0.f;

    const int mrow = (wid >> 2) * 32 + (lane & 15);   // + mt*16
    const int nrow = (wid & 3) * 32 + (lane & 15);    // + np*16
    const int chalf = lane >> 4;                      // 16B half within k16

    // hoisted swizzled ldsm offsets (chunk-relative), indexed by compile-time ks&3
    uint32_t swzA[2][4], swzB[2][4];
#pragma unroll
    for (int mt = 0; mt < 2; mt++) {
        int r = mrow + mt * 16;
#pragma unroll
        for (int ks = 0; ks < 4; ks++)
            swzA[mt][ks] = (uint32_t)(r * ROW_B + (((ks * 2 + chalf) ^ (r & 7)) << 4));
    }
#pragma unroll
    for (int np = 0; np < 2; np++) {
        int r = nrow + np * 16;
#pragma unroll
        for (int ks = 0; ks < 4; ks++)
            swzB[np][ks] = (uint32_t)(PLANE_B + r * ROW_B + (((ks * 2 + chalf) ^ (r & 7)) << 4));
    }

// ks_ in [0,8): chunk = ks_>>2, sub-k = ks_&3
#define LOAD_FRAGS(ks_, b_) do { \
        const uint32_t cb = ab + ((ks_) >> 2) * CHUNK_B; \
        ldsm4(fa[b_][0][0], fa[b_][0][1], fa[b_][0][2], fa[b_][0][3], cb + swzA[0][(ks_) & 3]); \
        ldsm4(fa[b_][1][0], fa[b_][1][1], fa[b_][1][2], fa[b_][1][3], cb + swzA[1][(ks_) & 3]); \
        ldsm4(fb[b_][0][0], fb[b_][0][1], fb[b_][0][2], fb[b_][0][3], cb + swzB[0][(ks_) & 3]); \
        ldsm4(fb[b_][1][0], fb[b_][1][1], fb[b_][1][2], fb[b_][1][3], cb + swzB[1][(ks_) & 3]); \
    } while (0)

    // prologue: 2 of 3 stages in flight (4 chunks)
    ISSUE_STAGE(0, 0);
    ISSUE_STAGE(1, 1);

#pragma unroll
    for (int it = 0; it < NITER; it++) {
        const int s = it % NSTAGE;                    // compile-time under full unroll
        if (it < NITER - 1) asm volatile("cp.async.wait_group 1;" ::: "memory");
        else                asm volatile("cp.async.wait_group 0;" ::: "memory");
        __syncthreads();   // proves all warps finished reading stage (it+2)%3 last iter

        if (it + 2 < NITER) ISSUE_STAGE((it + 2) % NSTAGE, it + 2);

        const uint32_t ab = sbase + s * STAGE_B;
        uint32_t fa[2][2][4], fb[2][2][4];
        LOAD_FRAGS(0, 0);
#pragma unroll
        for (int ks = 0; ks < 8; ks++) {
            const int cur = ks & 1;
            if (ks < 7) {
                switch (ks) {
                    case 0: LOAD_FRAGS(1, 1); break;
                    case 1: LOAD_FRAGS(2, 0); break;
                    case 2: LOAD_FRAGS(3, 1); break;
                    case 3: LOAD_FRAGS(4, 0); break;
                    case 4: LOAD_FRAGS(5, 1); break;
                    case 5: LOAD_FRAGS(6, 0); break;
                    default: LOAD_FRAGS(7, 1); break;
                }
            }
#pragma unroll
            for (int mt = 0; mt < 2; mt++)
#pragma unroll
                for (int nt = 0; nt < 4; nt++) {
                    int np = nt >> 1, od = nt & 1;
                    mma16816(D[mt][nt], fa[cur][mt], fb[cur][np][od], fb[cur][np][2 + od]);
                }
        }
    }

    // ---- epilogue: gate * (D + bias) scattered to token rows ----
    const int wm = (wid >> 2) * 32;
    const int wn = (wid & 3) * 32;
#pragma unroll
    for (int mt = 0; mt < 2; mt++) {
#pragma unroll
        for (int half = 0; half < 2; half++) {
            int r = wm + mt * 16 + (lane >> 2) + half * 8;
            int tok = s_tok[r];
            if (tok < 0) continue;
            float g = g_gate[tok];
            float* orow = out + (size_t)tok * H + bn + wn;
#pragma unroll
            for (int nt = 0; nt < 4; nt++) {
                int c = nt * 8 + (lane & 3) * 2;
                float2 bb = *(const float2*)(bias + (size_t)e * H + bn + wn + c);
                float2 v;
                v.x = g * (D[mt][nt][half * 2 + 0] + bb.x);
                v.y = g * (D[mt][nt][half * 2 + 1] + bb.y);
                *(float2*)(orow + c) = v;
            }
        }
    }
}

extern "C" void kernel_launch(void* const* d_in, const int* in_sizes, int n_in,
                              void* d_out, int out_size) {
    const float* x  = (const float*)d_in[0];   // [T, H]
    const float* wg = (const float*)d_in[1];   // [H, E]
    const float* W  = (const float*)d_in[2];   // [E, H, H]
    const float* b  = (const float*)d_in[3];   // [E, H]
    float* out = (float*)d_out;                // [T, H]

    cudaFuncSetAttribute(moe_gemm, cudaFuncAttributeMaxDynamicSharedMemorySize, GEMM_SMEM);

    route_conv_kernel<<<3072, 256>>>(x, wg, W);   // routing + W conversion overlapped
    scan_kernel<<<1, 1024>>>();
    dim3 grid(9, T_TOK / BM);                     // col 8 = dropped-row zeroing
    moe_gemm<<<grid, 512, GEMM_SMEM>>>(b, out);
}